// round 9
// baseline (speedup 1.0000x reference)
#include <cuda_runtime.h>

#define EPS 1e-5f
#define CAP 4096

// Device-global scratch (no allocations allowed).
__device__ float4 gF1[256];          // (A1, B1, a1, b13)
__device__ float4 gF2[256];          // (A2, B2, a2, b23)
__device__ float  gB21[256];
__device__ float  gB11[256];
__device__ float  gT[32 * 3136];
__device__ int    gN3, gN1;
__device__ int4   gCorr3[CAP];       // (o, c, k, d) with d = sign(w)-1 in {-1,-2}
__device__ int4   gCorr1[CAP];

__global__ void kZero() { gN3 = 0; gN1 = 0; }

__device__ __forceinline__ float sgnf(float v) {
    return (float)((v > 0.f) - (v < 0.f));
}

// Per-out-channel weight scale (mean|w|) -> fused BN constants; plus sparse
// list of weights whose sign is not +1 (exact handling of zero/neg weights).
__global__ __launch_bounds__(256) void kSC(
    const float* __restrict__ w3, const float* __restrict__ w1,
    const float* __restrict__ b11, const float* __restrict__ b12, const float* __restrict__ b13,
    const float* __restrict__ b21, const float* __restrict__ b22, const float* __restrict__ b23,
    const float* __restrict__ g1,  const float* __restrict__ be1, const float* __restrict__ m1, const float* __restrict__ v1,
    const float* __restrict__ g2,  const float* __restrict__ be2, const float* __restrict__ m2, const float* __restrict__ v2,
    const float* __restrict__ a1,  const float* __restrict__ a2)
{
    __shared__ float red[256];
    int b = blockIdx.x, t = threadIdx.x;
    float sum = 0.f;
    if (b < 256) {
        int o = b;
        const float* wp = w3 + (o * 256 + t) * 9;
        #pragma unroll
        for (int k = 0; k < 9; k++) {
            float w = wp[k];
            sum += fabsf(w);
            if (w <= 0.f) {
                int idx = atomicAdd(&gN3, 1);
                if (idx < CAP) gCorr3[idx] = make_int4(o, t, k, (w == 0.f) ? -1 : -2);
            }
        }
    } else {
        int o = b - 256;
        float w = w1[o * 256 + t];
        sum = fabsf(w);
        if (w <= 0.f) {
            int idx = atomicAdd(&gN1, 1);
            if (idx < CAP) gCorr1[idx] = make_int4(o, t, 0, (w == 0.f) ? -1 : -2);
        }
    }
    red[t] = sum;
    __syncthreads();
    #pragma unroll
    for (int s = 128; s > 0; s >>= 1) {
        if (t < s) red[t] += red[t + s];
        __syncthreads();
    }
    if (t == 0) {
        if (b < 256) {
            int c = b;
            float s3   = red[0] * (1.f / 2304.f);
            float inv1 = g1[c] / sqrtf(v1[c] + EPS);
            gF1[c]  = make_float4(inv1 * s3, be1[c] - m1[c] * inv1 + b12[c], a1[c], b13[c]);
            gB21[c] = b21[c];
            gB11[c] = b11[c];
        } else {
            int c = b - 256;
            float s1   = red[0] * (1.f / 256.f);
            float inv2 = g2[c] / sqrtf(v2[c] + EPS);
            gF2[c] = make_float4(inv2 * s1, be2[c] - m2[c] * inv2 + b22[c], a2[c], b23[c]);
        }
    }
}

// T pass: per-pixel channel-sum of sign(x + b11).
// thread = (pixel, channel-group): all global loads warp-coalesced, no transpose.
__global__ __launch_bounds__(256) void kT(const float* __restrict__ x,
                                          const float* __restrict__ b11)
{
    __shared__ int red[256];
    const int t = threadIdx.x, pix = t & 31, grp = t >> 5;
    const int n = blockIdx.y, p0 = blockIdx.x * 32;
    const float* xb = x + (size_t)n * 802816 + p0 + pix;

    int tl = 0;
    #pragma unroll 16
    for (int i = 0; i < 32; i++) {
        int c = grp * 32 + i;
        float v = __ldg(xb + (size_t)c * 3136) + __ldg(b11 + c);
        tl += (v > 0.f) - (v < 0.f);
    }
    red[t] = tl;
    __syncthreads();
    if (t < 32) {
        int s = 0;
        #pragma unroll
        for (int w = 0; w < 8; w++) s += red[w * 32 + t];
        gT[n * 3136 + p0 + t] = (float)s;
    }
}

// Main pass: 32 pixels x 256 channels per block; thread = (pixel, channel-group).
// Coalesced direct loads/stores, out1 in padded smem, 5 CTAs/SM.
__global__ __launch_bounds__(256, 5) void kMain(const float* __restrict__ x,
                                                float* __restrict__ out)
{
    __shared__ float o1s[256 * 33];
    __shared__ int   red[256];
    __shared__ float Ssm[32], T2sm[32];
    const int t = threadIdx.x, pix = t & 31, grp = t >> 5;
    // Reverse block order so wave 1 re-reads the x regions kT touched last (L2 reuse).
    const int n  = 31 - blockIdx.y;
    const int p0 = 3104 - blockIdx.x * 32;

    // S = 3x3 zero-padded box-sum of T for the block's 32 pixels.
    if (t < 32) {
        int p = p0 + t, h = p / 56, w0 = p % 56;
        const float* Tb = gT + n * 3136;
        float s = 0.f;
        #pragma unroll
        for (int dy = -1; dy <= 1; dy++) {
            int y = h + dy;
            if (y >= 0 && y < 56) {
                int rb = y * 56;
                #pragma unroll
                for (int dx = -1; dx <= 1; dx++) {
                    int xx = w0 + dx;
                    if (xx >= 0 && xx < 56) s += Tb[rb + xx];
                }
            }
        }
        Ssm[t] = s;
    }
    __syncthreads();

    int n3 = gN3; if (n3 > CAP) n3 = CAP;
    int n1 = gN1; if (n1 > CAP) n1 = CAP;

    const float* xb = x + (size_t)n * 802816 + p0 + pix;
    const float  Sv = Ssm[pix];

    // Phase 1: out1 per (channel, my pixel) -> smem; accumulate sign-sum T2.
    int t2 = 0;
    #pragma unroll 8
    for (int i = 0; i < 32; i++) {
        int c = grp * 32 + i;
        float4 F  = __ldg(gF1 + c);
        float  xv = __ldg(xb + (size_t)c * 3136);
        float  Sc = Sv;
        if (n3 > 0) {                           // rare exact-correction path
            float corr = 0.f;
            int p = p0 + pix, h = p / 56, w0 = p % 56;
            for (int e = 0; e < n3; e++) {
                int4 E = gCorr3[e];
                if (E.x == c) {
                    int dy = E.z / 3 - 1, dx = E.z % 3 - 1;
                    int y = h + dy, xx = w0 + dx;
                    if (y >= 0 && y < 56 && xx >= 0 && xx < 56) {
                        float vv = x[(size_t)n * 802816 + (size_t)E.y * 3136 + y * 56 + xx] + gB11[E.y];
                        corr += (float)E.w * sgnf(vv);
                    }
                }
            }
            Sc += corr;
        }
        float pre = __fmaf_rn(F.x, Sc, xv + F.y);
        float o1  = (pre > 0.f ? pre : F.z * pre) + F.w;
        o1s[c * 33 + pix] = o1;
        float u = o1 + __ldg(gB21 + c);
        t2 += (u > 0.f) - (u < 0.f);
    }
    red[t] = t2;
    __syncthreads();
    if (t < 32) {
        int s = 0;
        #pragma unroll
        for (int w = 0; w < 8; w++) s += red[w * 32 + t];
        T2sm[t] = (float)s;
    }
    __syncthreads();

    const float T2v = T2sm[pix];
    float* ob = out + (size_t)n * 802816 + p0 + pix;

    // Phase 2: out2 from out1 (smem) + T2; streaming coalesced stores.
    #pragma unroll 8
    for (int i = 0; i < 32; i++) {
        int c = grp * 32 + i;
        float4 F  = __ldg(gF2 + c);
        float  o1 = o1s[c * 33 + pix];
        float  Tv = T2v;
        if (n1 > 0) {                           // rare exact-correction path
            float corr = 0.f;
            for (int e = 0; e < n1; e++) {
                int4 E = gCorr1[e];
                if (E.x == c) {
                    float u = o1s[E.y * 33 + pix] + gB21[E.y];
                    corr += (float)E.w * sgnf(u);
                }
            }
            Tv += corr;
        }
        float pre = __fmaf_rn(F.x, Tv, o1 + F.y);
        float o2  = (pre > 0.f ? pre : F.z * pre) + F.w;
        __stcs(ob + (size_t)c * 3136, o2);
    }
}

extern "C" void kernel_launch(void* const* d_in, const int* in_sizes, int n_in,
                              void* d_out, int out_size) {
    const float* x   = (const float*)d_in[0];
    const float* w3  = (const float*)d_in[1];
    const float* w1  = (const float*)d_in[2];
    const float* b11 = (const float*)d_in[3];
    const float* b12 = (const float*)d_in[4];
    const float* b13 = (const float*)d_in[5];
    const float* b21 = (const float*)d_in[6];
    const float* b22 = (const float*)d_in[7];
    const float* b23 = (const float*)d_in[8];
    const float* g1  = (const float*)d_in[9];
    const float* be1 = (const float*)d_in[10];
    const float* m1  = (const float*)d_in[11];
    const float* v1  = (const float*)d_in[12];
    const float* g2  = (const float*)d_in[13];
    const float* be2 = (const float*)d_in[14];
    const float* m2  = (const float*)d_in[15];
    const float* v2  = (const float*)d_in[16];
    const float* a1  = (const float*)d_in[17];
    const float* a2  = (const float*)d_in[18];
    float* out = (float*)d_out;

    kZero<<<1, 1>>>();
    kSC<<<512, 256>>>(w3, w1, b11, b12, b13, b21, b22, b23,
                      g1, be1, m1, v1, g2, be2, m2, v2, a1, a2);
    kT<<<dim3(98, 32), 256>>>(x, b11);
    kMain<<<dim3(98, 32), 256>>>(x, out);
}

// round 10
// speedup vs baseline: 1.6008x; 1.6008x over previous
#include <cuda_runtime.h>

#define EPS 1e-5f
#define CAP 4096

// Device-global scratch (no allocations allowed).
__device__ float4 gF1[256];          // (A1, B1, a1, b13)
__device__ float4 gF2[256];          // (A2, B2, a2, b23)
__device__ float  gB21[256];
__device__ float  gB11[256];
__device__ float  gT[32 * 3136];
__device__ int    gN3, gN1;
__device__ int4   gCorr3[CAP];       // (o, c, k, d) with d = sign(w)-1 in {-1,-2}
__device__ int4   gCorr1[CAP];

__global__ void kZero() { gN3 = 0; gN1 = 0; }

__device__ __forceinline__ float sgnf(float v) {
    return (float)((v > 0.f) - (v < 0.f));
}

// Per-out-channel weight scale (mean|w|) -> fused BN constants; plus sparse
// list of weights whose sign is not +1 (exact handling of zero/neg weights).
__global__ __launch_bounds__(256) void kSC(
    const float* __restrict__ w3, const float* __restrict__ w1,
    const float* __restrict__ b11, const float* __restrict__ b12, const float* __restrict__ b13,
    const float* __restrict__ b21, const float* __restrict__ b22, const float* __restrict__ b23,
    const float* __restrict__ g1,  const float* __restrict__ be1, const float* __restrict__ m1, const float* __restrict__ v1,
    const float* __restrict__ g2,  const float* __restrict__ be2, const float* __restrict__ m2, const float* __restrict__ v2,
    const float* __restrict__ a1,  const float* __restrict__ a2)
{
    __shared__ float red[256];
    int b = blockIdx.x, t = threadIdx.x;
    float sum = 0.f;
    if (b < 256) {
        int o = b;
        const float* wp = w3 + (o * 256 + t) * 9;
        #pragma unroll
        for (int k = 0; k < 9; k++) {
            float w = wp[k];
            sum += fabsf(w);
            if (w <= 0.f) {
                int idx = atomicAdd(&gN3, 1);
                if (idx < CAP) gCorr3[idx] = make_int4(o, t, k, (w == 0.f) ? -1 : -2);
            }
        }
    } else {
        int o = b - 256;
        float w = w1[o * 256 + t];
        sum = fabsf(w);
        if (w <= 0.f) {
            int idx = atomicAdd(&gN1, 1);
            if (idx < CAP) gCorr1[idx] = make_int4(o, t, 0, (w == 0.f) ? -1 : -2);
        }
    }
    red[t] = sum;
    __syncthreads();
    #pragma unroll
    for (int s = 128; s > 0; s >>= 1) {
        if (t < s) red[t] += red[t + s];
        __syncthreads();
    }
    if (t == 0) {
        if (b < 256) {
            int c = b;
            float s3   = red[0] * (1.f / 2304.f);
            float inv1 = g1[c] / sqrtf(v1[c] + EPS);
            gF1[c]  = make_float4(inv1 * s3, be1[c] - m1[c] * inv1 + b12[c], a1[c], b13[c]);
            gB21[c] = b21[c];
            gB11[c] = b11[c];
        } else {
            int c = b - 256;
            float s1   = red[0] * (1.f / 256.f);
            float inv2 = g2[c] / sqrtf(v2[c] + EPS);
            gF2[c] = make_float4(inv2 * s1, be2[c] - m2[c] * inv2 + b22[c], a2[c], b23[c]);
        }
    }
}

// T pass: per-pixel channel-sum of sign(x + b11). All loads LDG.128.
// thread = (float4-pixel v, channel-group grp): 32 groups x 8 channels.
__global__ __launch_bounds__(256) void kT(const float* __restrict__ x,
                                          const float* __restrict__ b11)
{
    __shared__ int4 red4[256];
    const int t = threadIdx.x, v = t & 7, grp = t >> 3;
    const int n = blockIdx.y, p0 = blockIdx.x * 32;
    const float4* xb4 = (const float4*)(x + (size_t)n * 802816 + p0) + v;

    int4 acc = make_int4(0, 0, 0, 0);
    #pragma unroll
    for (int i = 0; i < 8; i++) {
        int c = grp * 8 + i;
        float4 q = __ldg(xb4 + (size_t)c * 784);   // 3136/4
        float bc = __ldg(b11 + c);
        acc.x += (q.x + bc > 0.f) - (q.x + bc < 0.f);
        acc.y += (q.y + bc > 0.f) - (q.y + bc < 0.f);
        acc.z += (q.z + bc > 0.f) - (q.z + bc < 0.f);
        acc.w += (q.w + bc > 0.f) - (q.w + bc < 0.f);
    }
    red4[grp * 8 + v] = acc;
    __syncthreads();
    if (t < 32) {
        const int* r = (const int*)red4;
        int s = 0;
        #pragma unroll
        for (int g = 0; g < 32; g++) s += r[g * 32 + t];
        gT[n * 3136 + p0 + t] = (float)s;
    }
}

// Main pass: 32 pixels x 256 channels per block; thread = (float4-pixel, 8-ch group).
// 128-bit global & shared accesses throughout; out1 tile in smem (32 KB).
__global__ __launch_bounds__(256, 5) void kMain(const float* __restrict__ x,
                                                float* __restrict__ out)
{
    __shared__ float4 o1s4[256 * 8];       // [channel][v] : 32 KB
    __shared__ int4   red4[256];
    __shared__ float  Ssm[32], T2sm[32];
    const int t = threadIdx.x, v = t & 7, grp = t >> 3;
    // Reverse block order so wave 1 re-reads the x regions kT touched last (L2 reuse).
    const int n  = 31 - blockIdx.y;
    const int p0 = 3104 - blockIdx.x * 32;

    // S = 3x3 zero-padded box-sum of T for the block's 32 pixels.
    if (t < 32) {
        int p = p0 + t, h = p / 56, w0 = p % 56;
        const float* Tb = gT + n * 3136;
        float s = 0.f;
        #pragma unroll
        for (int dy = -1; dy <= 1; dy++) {
            int y = h + dy;
            if (y >= 0 && y < 56) {
                int rb = y * 56;
                #pragma unroll
                for (int dx = -1; dx <= 1; dx++) {
                    int xx = w0 + dx;
                    if (xx >= 0 && xx < 56) s += Tb[rb + xx];
                }
            }
        }
        Ssm[t] = s;
    }
    __syncthreads();

    int n3 = gN3; if (n3 > CAP) n3 = CAP;
    int n1 = gN1; if (n1 > CAP) n1 = CAP;

    const float4* xb4 = (const float4*)(x + (size_t)n * 802816 + p0) + v;
    const float4  Sv4 = ((const float4*)Ssm)[v];

    // Phase 1: out1 per (channel, my 4 pixels) -> smem; accumulate sign-sum T2.
    int4 t2 = make_int4(0, 0, 0, 0);
    #pragma unroll
    for (int i = 0; i < 8; i++) {
        int c = grp * 8 + i;
        float4 F  = __ldg(gF1 + c);
        float4 xv = __ldg(xb4 + (size_t)c * 784);
        float4 Sc = Sv4;
        if (n3 > 0) {                           // rare exact-correction path
            #pragma unroll
            for (int k = 0; k < 4; k++) {
                float corr = 0.f;
                int p = p0 + v * 4 + k, h = p / 56, w0 = p % 56;
                for (int e = 0; e < n3; e++) {
                    int4 E = gCorr3[e];
                    if (E.x == c) {
                        int dy = E.z / 3 - 1, dx = E.z % 3 - 1;
                        int y = h + dy, xx = w0 + dx;
                        if (y >= 0 && y < 56 && xx >= 0 && xx < 56) {
                            float vv = x[(size_t)n * 802816 + (size_t)E.y * 3136 + y * 56 + xx] + gB11[E.y];
                            corr += (float)E.w * sgnf(vv);
                        }
                    }
                }
                ((float*)&Sc)[k] += corr;
            }
        }
        float b21c = __ldg(gB21 + c);
        float4 o1;
        float pre;
        pre = __fmaf_rn(F.x, Sc.x, xv.x + F.y); o1.x = (pre > 0.f ? pre : F.z * pre) + F.w;
        pre = __fmaf_rn(F.x, Sc.y, xv.y + F.y); o1.y = (pre > 0.f ? pre : F.z * pre) + F.w;
        pre = __fmaf_rn(F.x, Sc.z, xv.z + F.y); o1.z = (pre > 0.f ? pre : F.z * pre) + F.w;
        pre = __fmaf_rn(F.x, Sc.w, xv.w + F.y); o1.w = (pre > 0.f ? pre : F.z * pre) + F.w;
        o1s4[c * 8 + v] = o1;
        t2.x += (o1.x + b21c > 0.f) - (o1.x + b21c < 0.f);
        t2.y += (o1.y + b21c > 0.f) - (o1.y + b21c < 0.f);
        t2.z += (o1.z + b21c > 0.f) - (o1.z + b21c < 0.f);
        t2.w += (o1.w + b21c > 0.f) - (o1.w + b21c < 0.f);
    }
    red4[grp * 8 + v] = t2;
    __syncthreads();
    if (t < 32) {
        const int* r = (const int*)red4;
        int s = 0;
        #pragma unroll
        for (int g = 0; g < 32; g++) s += r[g * 32 + t];
        T2sm[t] = (float)s;
    }
    __syncthreads();

    const float4 T2v4 = ((const float4*)T2sm)[v];
    float4* ob4 = (float4*)(out + (size_t)n * 802816 + p0) + v;

    // Phase 2: out2 from out1 (smem) + T2; streaming 128-bit stores.
    #pragma unroll
    for (int i = 0; i < 8; i++) {
        int c = grp * 8 + i;
        float4 F  = __ldg(gF2 + c);
        float4 o1 = o1s4[c * 8 + v];
        float4 Tv = T2v4;
        if (n1 > 0) {                           // rare exact-correction path
            #pragma unroll
            for (int k = 0; k < 4; k++) {
                float corr = 0.f;
                int p = v * 4 + k;
                for (int e = 0; e < n1; e++) {
                    int4 E = gCorr1[e];
                    if (E.x == c) {
                        float u = ((const float*)o1s4)[E.y * 32 + p] + gB21[E.y];
                        corr += (float)E.w * sgnf(u);
                    }
                }
                ((float*)&Tv)[k] += corr;
            }
        }
        float4 o2;
        float pre;
        pre = __fmaf_rn(F.x, Tv.x, o1.x + F.y); o2.x = (pre > 0.f ? pre : F.z * pre) + F.w;
        pre = __fmaf_rn(F.x, Tv.y, o1.y + F.y); o2.y = (pre > 0.f ? pre : F.z * pre) + F.w;
        pre = __fmaf_rn(F.x, Tv.z, o1.z + F.y); o2.z = (pre > 0.f ? pre : F.z * pre) + F.w;
        pre = __fmaf_rn(F.x, Tv.w, o1.w + F.y); o2.w = (pre > 0.f ? pre : F.z * pre) + F.w;
        __stcs(ob4 + (size_t)c * 784, o2);
    }
}

extern "C" void kernel_launch(void* const* d_in, const int* in_sizes, int n_in,
                              void* d_out, int out_size) {
    const float* x   = (const float*)d_in[0];
    const float* w3  = (const float*)d_in[1];
    const float* w1  = (const float*)d_in[2];
    const float* b11 = (const float*)d_in[3];
    const float* b12 = (const float*)d_in[4];
    const float* b13 = (const float*)d_in[5];
    const float* b21 = (const float*)d_in[6];
    const float* b22 = (const float*)d_in[7];
    const float* b23 = (const float*)d_in[8];
    const float* g1  = (const float*)d_in[9];
    const float* be1 = (const float*)d_in[10];
    const float* m1  = (const float*)d_in[11];
    const float* v1  = (const float*)d_in[12];
    const float* g2  = (const float*)d_in[13];
    const float* be2 = (const float*)d_in[14];
    const float* m2  = (const float*)d_in[15];
    const float* v2  = (const float*)d_in[16];
    const float* a1  = (const float*)d_in[17];
    const float* a2  = (const float*)d_in[18];
    float* out = (float*)d_out;

    kZero<<<1, 1>>>();
    kSC<<<512, 256>>>(w3, w1, b11, b12, b13, b21, b22, b23,
                      g1, be1, m1, v1, g2, be2, m2, v2, a1, a2);
    kT<<<dim3(98, 32), 256>>>(x, b11);
    kMain<<<dim3(98, 32), 256>>>(x, out);
}